// round 1
// baseline (speedup 1.0000x reference)
#include <cuda_runtime.h>

// Problem constants (fixed shapes from setup_inputs)
#define IMG_H 360
#define IMG_W 640
#define N_ROI 128
#define N_CH  196     // GROUP_C(4) * 7 * 7
#define PDIM  72      // patch dim with halo: roi <= 64 + 2 halo + slack
#define SMEM_BYTES (3 * PDIM * PDIM * 4)   // 62208 B dynamic smem

// Fused: 3x3 SAME conv + bias + ReLU (computed on the fly per bin pixel)
//        -> ps_roi_pool (GROUP_C=4, out 7x7) -> mean over 7x7 -> out [128,4]
__global__ __launch_bounds__(224, 1)
void fused_mv_psroi_kernel(const float* __restrict__ mv,     // [2,3,360,640]
                           const float* __restrict__ boxes,  // [128,5]
                           const float* __restrict__ msc,    // [1,2]
                           const float* __restrict__ cw,     // [196,3,3,3]
                           const float* __restrict__ cb,     // [196]
                           float* __restrict__ out)          // [128,4]
{
    extern __shared__ float patch[];        // [3][PDIM][PDIM]
    __shared__ float spool[N_CH];

    const int k   = blockIdx.x;
    const int tid = threadIdx.x;

    // ---- box / bin geometry (all threads compute, cheap & uniform) ----
    const float s  = __ldg(&msc[0]);
    const int   bi = (int)__ldg(&boxes[k * 5 + 0]);
    // jnp.round == round-half-to-even == rintf
    const float x1 = rintf(__ldg(&boxes[k * 5 + 1]) * s);
    const float y1 = rintf(__ldg(&boxes[k * 5 + 2]) * s);
    const float x2 = rintf(__ldg(&boxes[k * 5 + 3]) * s);
    const float y2 = rintf(__ldg(&boxes[k * 5 + 4]) * s);

    const float roi_w = fmaxf(x2 - x1, 0.1f);
    const float roi_h = fmaxf(y2 - y1, 0.1f);
    const float bin_h = roi_h / 7.0f;   // IEEE div, matches jnp
    const float bin_w = roi_w / 7.0f;

    // Whole-ROI spatial extent (ph=0 start .. ph=6 end), as reference computes it
    const int hs0 = min(max((int)floorf(y1), 0), IMG_H);
    const int he6 = min(max((int)ceilf(7.0f * bin_h + y1), 0), IMG_H);
    const int ws0 = min(max((int)floorf(x1), 0), IMG_W);
    const int we6 = min(max((int)ceilf(7.0f * bin_w + x1), 0), IMG_W);

    const int py0 = hs0 - 1;                          // patch origin (incl. halo)
    const int px0 = ws0 - 1;
    int PHt = he6 - hs0 + 2;                          // rows hs0-1 .. he6
    int PWt = we6 - ws0 + 2;
    PHt = min(max(PHt, 0), PDIM);                     // safety clamp
    PWt = min(max(PWt, 0), PDIM);

    // ---- stage input patch into smem with zero halo (SAME padding) ----
    const int total = 3 * PHt * PWt;
    const float* img = mv + (size_t)bi * 3 * IMG_H * IMG_W;
    for (int i = tid; i < total; i += 224) {
        const int ic = i / (PHt * PWt);
        const int r  = (i / PWt) % PHt;
        const int cc = i % PWt;
        const int gy = py0 + r;
        const int gx = px0 + cc;
        float v = 0.0f;
        if ((unsigned)gy < IMG_H && (unsigned)gx < IMG_W)
            v = __ldg(&img[(ic * IMG_H + gy) * IMG_W + gx]);
        patch[(ic * PDIM + r) * PDIM + cc] = v;
    }
    __syncthreads();

    // ---- per-thread: one (g, ph, pw) bin ----
    if (tid < N_CH) {
        // lanes 4j..4j+3 share the same bin rect -> smem broadcast + low divergence
        const int g   = tid & 3;
        const int bin = tid >> 2;
        const int ph  = bin / 7;
        const int pw  = bin % 7;
        const int c   = (g * 7 + ph) * 7 + pw;

        float wreg[27];
        #pragma unroll
        for (int j = 0; j < 27; j++) wreg[j] = __ldg(&cw[c * 27 + j]);
        const float bias = __ldg(&cb[c]);

        const float fph = (float)ph, fpw = (float)pw;
        const int hs = min(max((int)floorf(fph * bin_h + y1), 0), IMG_H);
        const int he = min(max((int)ceilf((fph + 1.0f) * bin_h + y1), 0), IMG_H);
        const int ws = min(max((int)floorf(fpw * bin_w + x1), 0), IMG_W);
        const int we = min(max((int)ceilf((fpw + 1.0f) * bin_w + x1), 0), IMG_W);
        const int area = (he - hs) * (we - ws);

        float sum = 0.0f;
        for (int yy = hs; yy < he; ++yy) {
            const int ry = yy - py0;           // window rows ry-1..ry+1 (halo safe)
            float win[3][3][3];                // [ic][ky][col 0..2]
            const int lx0 = ws - px0;          // >= 1
            #pragma unroll
            for (int ic = 0; ic < 3; ic++)
                #pragma unroll
                for (int ky = 0; ky < 3; ky++) {
                    const int base = (ic * PDIM + (ry - 1 + ky)) * PDIM;
                    win[ic][ky][0] = patch[base + lx0 - 1];
                    win[ic][ky][1] = patch[base + lx0];
                }
            for (int xx = ws; xx < we; ++xx) {
                const int lx = xx - px0;
                #pragma unroll
                for (int ic = 0; ic < 3; ic++)
                    #pragma unroll
                    for (int ky = 0; ky < 3; ky++)
                        win[ic][ky][2] =
                            patch[(ic * PDIM + (ry - 1 + ky)) * PDIM + lx + 1];

                float v = bias;
                #pragma unroll
                for (int ic = 0; ic < 3; ic++)
                    #pragma unroll
                    for (int ky = 0; ky < 3; ky++)
                        #pragma unroll
                        for (int kx = 0; kx < 3; kx++)
                            v = fmaf(win[ic][ky][kx], wreg[ic * 9 + ky * 3 + kx], v);
                sum += fmaxf(v, 0.0f);         // ReLU, then bin accumulation

                #pragma unroll
                for (int ic = 0; ic < 3; ic++)
                    #pragma unroll
                    for (int ky = 0; ky < 3; ky++) {
                        win[ic][ky][0] = win[ic][ky][1];
                        win[ic][ky][1] = win[ic][ky][2];
                    }
            }
        }
        spool[tid] = (area > 0) ? (sum / (float)area) : 0.0f;
    }
    __syncthreads();

    // ---- mean over the 49 bins of each group -> out[k,g] ----
    if (tid < 4) {
        float acc = 0.0f;
        #pragma unroll
        for (int b2 = 0; b2 < 49; b2++) acc += spool[b2 * 4 + tid];
        out[k * 4 + tid] = acc / 49.0f;
    }
}

extern "C" void kernel_launch(void* const* d_in, const int* in_sizes, int n_in,
                              void* d_out, int out_size)
{
    const float* mv    = (const float*)d_in[0];  // motion_vectors [2,3,360,640]
    const float* boxes = (const float*)d_in[1];  // boxes_prev [128,5]
    const float* msc   = (const float*)d_in[2];  // motion_vector_scale [1,2]
    const float* cw    = (const float*)d_in[3];  // conv_w [196,3,3,3]
    const float* cb    = (const float*)d_in[4];  // conv_b [196]
    float* out         = (float*)d_out;          // [128,4]

    cudaFuncSetAttribute(fused_mv_psroi_kernel,
                         cudaFuncAttributeMaxDynamicSharedMemorySize, SMEM_BYTES);
    fused_mv_psroi_kernel<<<N_ROI, 224, SMEM_BYTES>>>(mv, boxes, msc, cw, cb, out);
}